// round 6
// baseline (speedup 1.0000x reference)
#include <cuda_runtime.h>
#include <cstdint>
#include <math.h>

#define B_   64
#define T_   512
#define D_   1024
#define H_   1024
#define NG   4096       // 4*H
#define CHUNK 128       // h k-slice per pipeline stage
#define NKC  (H_/CHUNK) // 8
#define SMEM_LSTM ((32*1024 + 2*64*CHUNK) * 4)   // 196,608 bytes

// ---------------- static device scratch (no allocations allowed) ----------------
__device__ float g_xg[(size_t)T_ * B_ * NG];   // [t][b][4H] : x @ w_ih^T + b_ih + b_hh
__device__ float g_ht[2][B_ * H_];             // ping-pong h, [b][k] layout
__device__ float g_c[B_ * H_];                 // cell state,  [b][j] layout

// ---------------- f32x2 packed-math helpers (FFMA2 path, 2x fp32 rate) ----------
typedef unsigned long long ull;

__device__ __forceinline__ void fma2(ull& acc, ull a, ull b) {
    asm("fma.rn.f32x2 %0, %1, %2, %0;" : "+l"(acc) : "l"(a), "l"(b));
}
__device__ __forceinline__ ull dup2(float a) {
    ull r; asm("mov.b64 %0, {%1, %1};" : "=l"(r) : "f"(a)); return r;
}
__device__ __forceinline__ float2 unpk(ull v) {
    float2 r; asm("mov.b64 {%0, %1}, %2;" : "=f"(r.x), "=f"(r.y) : "l"(v)); return r;
}
__device__ __forceinline__ float redu2(ull v) { float2 p = unpk(v); return p.x + p.y; }

__device__ __forceinline__ void cp_async16(float* s, const float* g) {
    unsigned saddr = (unsigned)__cvta_generic_to_shared(s);
    asm volatile("cp.async.cg.shared.global [%0], [%1], 16;" :: "r"(saddr), "l"(g));
}

// =================================================================================
// Kernel 0: zero h0 and c (d_out is poisoned; our state must start clean each call)
// =================================================================================
__global__ void zero_init() {
    int i = blockIdx.x * blockDim.x + threadIdx.x;   // 512*256 = 131072 threads
    if (i < B_ * H_) { g_ht[0][i] = 0.f; g_c[i] = 0.f; }
}

// =================================================================================
// Kernel A: xg[t][b][n] = sum_d x[b,t,d] * w_ih[n,d] + b_ih[n] + b_hh[n]
// 128x128x8 fp32 SGEMM, 256 threads, 8x8 per thread via f32x2 (pack along N).
// =================================================================================
__global__ __launch_bounds__(256) void sgemm_ih(
    const float* __restrict__ X, const float* __restrict__ W,
    const float* __restrict__ bih, const float* __restrict__ bhh)
{
    __shared__ float As[8][128];
    __shared__ float Bs[8][128];
    const int tid = threadIdx.x;
    const int m0 = blockIdx.y * 128;
    const int n0 = blockIdx.x * 128;
    const int lr = tid >> 1;
    const int lk = (tid & 1) << 2;
    const float* Ag = X + (size_t)(m0 + lr) * D_ + lk;
    const float* Bg = W + (size_t)(n0 + lr) * D_ + lk;
    const int tx = tid & 15;
    const int ty = tid >> 4;
    const int rm = ty << 2;
    const int rn = tx << 2;

    ull acc2[8][4];
    #pragma unroll
    for (int i = 0; i < 8; i++)
        #pragma unroll
        for (int j = 0; j < 4; j++) acc2[i][j] = 0ull;

    float4 av = *(const float4*)Ag;
    float4 bv = *(const float4*)Bg;

    for (int k0 = 0; k0 < D_; k0 += 8) {
        As[lk+0][lr] = av.x; As[lk+1][lr] = av.y; As[lk+2][lr] = av.z; As[lk+3][lr] = av.w;
        Bs[lk+0][lr] = bv.x; Bs[lk+1][lr] = bv.y; Bs[lk+2][lr] = bv.z; Bs[lk+3][lr] = bv.w;
        __syncthreads();
        if (k0 + 8 < D_) {                          // prefetch next tile into regs
            av = *(const float4*)(Ag + k0 + 8);
            bv = *(const float4*)(Bg + k0 + 8);
        }
        #pragma unroll
        for (int k = 0; k < 8; k++) {
            float a[8];
            *(float4*)&a[0] = *(const float4*)&As[k][rm];
            *(float4*)&a[4] = *(const float4*)&As[k][rm + 64];
            ulonglong2 bA = *(const ulonglong2*)&Bs[k][rn];       // cols rn..rn+3
            ulonglong2 bB = *(const ulonglong2*)&Bs[k][rn + 64];  // cols rn+64..+67
            #pragma unroll
            for (int i = 0; i < 8; i++) {
                ull ad = dup2(a[i]);
                fma2(acc2[i][0], ad, bA.x);
                fma2(acc2[i][1], ad, bA.y);
                fma2(acc2[i][2], ad, bB.x);
                fma2(acc2[i][3], ad, bB.y);
            }
        }
        __syncthreads();
    }

    float biasv[8];
    #pragma unroll
    for (int j = 0; j < 8; j++) {
        int n = n0 + ((j < 4) ? (rn + j) : (64 + rn + j - 4));
        biasv[j] = bih[n] + bhh[n];
    }
    #pragma unroll
    for (int i = 0; i < 8; i++) {
        int m = m0 + ((i < 4) ? (rm + i) : (64 + rm + i - 4));
        int bb = m >> 9;            // batch   (m = b*512 + t)
        int tt = m & 511;           // timestep
        float* dst = g_xg + (size_t)(tt * B_ + bb) * NG;
        float2 u0 = unpk(acc2[i][0]), u1 = unpk(acc2[i][1]);
        float2 u2 = unpk(acc2[i][2]), u3 = unpk(acc2[i][3]);
        float4 v0 = make_float4(u0.x + biasv[0], u0.y + biasv[1],
                                u1.x + biasv[2], u1.y + biasv[3]);
        float4 v1 = make_float4(u2.x + biasv[4], u2.y + biasv[5],
                                u3.x + biasv[6], u3.y + biasv[7]);
        *(float4*)(dst + n0 + rn)      = v0;
        *(float4*)(dst + n0 + 64 + rn) = v1;
    }
}

// =================================================================================
// Kernel B: ONE LSTM timestep. 128 blocks x 128 threads.
// Block bid owns h columns j0=bid*8 .. +8 (all 64 batches, all 4 gates).
// Thread (tb = tid>>3 in 0..15, tg = tid&7): 4 batches (4tb..+3) x col (j0+tg) x 4 gates.
// w_hh slice (32 rows x 1024) staged in smem each step (hot in L2), k-XOR-swizzled
// so the 8 tg-lanes of a phase hit all 32 banks. h broadcast across tg lanes.
// Inner math: f32x2 packed along K -> 32 FFMA2 + 8 LDS.128 per k-quad (fma-bound).
// =================================================================================
__global__ __launch_bounds__(128, 1) void lstm_step(const float* __restrict__ whh, int t)
{
    extern __shared__ float smem[];
    float* ws = smem;                 // 32 * 1024 floats (w slice, row r = g*8+q, swizzled)
    float* hs = smem + 32 * 1024;     // 2 * 64 * CHUNK floats (h staging, [b][k'])
    const int tid = threadIdx.x;
    const int tb  = tid >> 3;         // 0..15  batch quad
    const int tg  = tid & 7;          // 0..7   col within block
    const int j0  = blockIdx.x * 8;
    const int j   = j0 + tg;

    const float* ht_r = g_ht[t & 1];
    float*       ht_w = g_ht[(t + 1) & 1];

    // --- stage w slice (32 x 1024 floats = 128KB) via cp.async, swizzled ---
    for (int idx = tid; idx < 32 * 256; idx += 128) {
        int r  = idx >> 8;                 // local row 0..31,  r = g*8 + q
        int kq = (idx & 255) << 2;         // float index 0..1020
        int g  = r >> 3, q = r & 7;
        const float* src = whh + (size_t)(g * H_ + j0 + q) * H_ + kq;
        float* dst = ws + r * 1024 + (kq ^ (q << 2));
        cp_async16(dst, src);
    }
    asm volatile("cp.async.commit_group;" ::: "memory");
    // --- stage h chunk 0 ---
    for (int idx = tid; idx < 64 * (CHUNK / 4); idx += 128) {
        int b  = idx / (CHUNK / 4);
        int k4 = (idx % (CHUNK / 4)) << 2;
        cp_async16(hs + b * CHUNK + k4, ht_r + b * H_ + k4);
    }
    asm volatile("cp.async.commit_group;" ::: "memory");

    // --- prefetch xg gate contributions + cell state while cp.async flies ---
    float xv[4][4];
    float cst[4];
    {
        const float* xb = g_xg + (size_t)(t * B_) * NG + j;
        #pragma unroll
        for (int i = 0; i < 4; i++) {
            int b = (tb << 2) + i;
            const float* p = xb + (size_t)b * NG;
            xv[i][0] = p[0]; xv[i][1] = p[H_]; xv[i][2] = p[2 * H_]; xv[i][3] = p[3 * H_];
            cst[i] = g_c[b * H_ + j];
        }
    }

    ull acc[4][4];
    #pragma unroll
    for (int i = 0; i < 4; i++)
        #pragma unroll
        for (int g = 0; g < 4; g++) acc[i][g] = 0ull;

    asm volatile("cp.async.wait_group 0;" ::: "memory");
    __syncthreads();

    #pragma unroll 1
    for (int kc = 0; kc < NKC; kc++) {
        if (kc + 1 < NKC) {                 // prefetch next h chunk
            float* dst = hs + ((kc + 1) & 1) * (64 * CHUNK);
            const float* src = ht_r + (kc + 1) * CHUNK;
            for (int idx = tid; idx < 64 * (CHUNK / 4); idx += 128) {
                int b  = idx / (CHUNK / 4);
                int k4 = (idx % (CHUNK / 4)) << 2;
                cp_async16(dst + b * CHUNK + k4, src + b * H_ + k4);
            }
            asm volatile("cp.async.commit_group;" ::: "memory");
        }
        const float* hb = hs + (kc & 1) * (64 * CHUNK) + (tb << 2) * CHUNK;
        const float* wb = ws;
        const int kbase = kc * CHUNK;
        #pragma unroll 4
        for (int kk = 0; kk < CHUNK; kk += 4) {
            ulonglong2 hv[4];
            #pragma unroll
            for (int i = 0; i < 4; i++)
                hv[i] = *(const ulonglong2*)(hb + i * CHUNK + kk);
            ulonglong2 wv[4];
            const int kidx = (kbase + kk) ^ (tg << 2);
            #pragma unroll
            for (int g = 0; g < 4; g++)
                wv[g] = *(const ulonglong2*)(wb + (g * 8 + tg) * 1024 + kidx);
            #pragma unroll
            for (int i = 0; i < 4; i++) {
                #pragma unroll
                for (int g = 0; g < 4; g++) {
                    fma2(acc[i][g], hv[i].x, wv[g].x);
                    fma2(acc[i][g], hv[i].y, wv[g].y);
                }
            }
        }
        if (kc + 1 < NKC)
            asm volatile("cp.async.wait_group 0;" ::: "memory");
        __syncthreads();
    }

    // --- gates + pointwise cell update ---
    #pragma unroll
    for (int i = 0; i < 4; i++) {
        int b = (tb << 2) + i;
        float gi = redu2(acc[i][0]) + xv[i][0];
        float gf = redu2(acc[i][1]) + xv[i][1];
        float gg = redu2(acc[i][2]) + xv[i][2];
        float go = redu2(acc[i][3]) + xv[i][3];
        float s_i = 1.f / (1.f + expf(-gi));
        float s_f = 1.f / (1.f + expf(-gf));
        float t_g = tanhf(gg);
        float s_o = 1.f / (1.f + expf(-go));
        float cn  = s_f * cst[i] + s_i * t_g;
        g_c[b * H_ + j]  = cn;
        ht_w[b * H_ + j] = s_o * tanhf(cn);
    }
}

// =================================================================================
// Kernel C: heads. h_final in g_ht[0], [b][k]. Output: gender[64,2] ++ age[64,7].
// =================================================================================
__global__ void heads_kernel(const float* __restrict__ wg, const float* __restrict__ bg,
                             const float* __restrict__ wa, const float* __restrict__ ba,
                             float* __restrict__ out)
{
    int o = blockIdx.x;        // 0..8  (0,1 -> gender; 2..8 -> age)
    int b = threadIdx.x;       // 0..63
    const float* w = (o < 2) ? (wg + o * H_) : (wa + (o - 2) * H_);
    float bias = (o < 2) ? bg[o] : ba[o - 2];
    const float* h = g_ht[0] + (size_t)b * H_;
    float s0 = 0.f, s1 = 0.f, s2 = 0.f, s3 = 0.f;
    for (int k = 0; k < H_; k += 4) {
        s0 += h[k + 0] * w[k + 0];
        s1 += h[k + 1] * w[k + 1];
        s2 += h[k + 2] * w[k + 2];
        s3 += h[k + 3] * w[k + 3];
    }
    float s = bias + ((s0 + s1) + (s2 + s3));
    if (o < 2) out[b * 2 + o] = s;
    else       out[B_ * 2 + b * 7 + (o - 2)] = s;
}

// =================================================================================
extern "C" void kernel_launch(void* const* d_in, const int* in_sizes, int n_in,
                              void* d_out, int out_size)
{
    const float* x   = (const float*)d_in[0];
    const float* wih = (const float*)d_in[1];
    const float* whh = (const float*)d_in[2];
    const float* bih = (const float*)d_in[3];
    const float* bhh = (const float*)d_in[4];
    const float* wg  = (const float*)d_in[5];
    const float* bg  = (const float*)d_in[6];
    const float* wa  = (const float*)d_in[7];
    const float* ba  = (const float*)d_in[8];
    float* out = (float*)d_out;

    static int smem_set = 0;
    if (!smem_set) {
        cudaFuncSetAttribute(lstm_step, cudaFuncAttributeMaxDynamicSharedMemorySize, SMEM_LSTM);
        smem_set = 1;
    }

    zero_init<<<(B_ * H_ + 255) / 256, 256>>>();

    dim3 gA(NG / 128, (B_ * T_) / 128);          // 32 x 256 blocks
    sgemm_ih<<<gA, 256>>>(x, wih, bih, bhh);

    for (int t = 0; t < T_; t++)
        lstm_step<<<128, 128, SMEM_LSTM>>>(whh, t);

    heads_kernel<<<9, 64>>>(wg, bg, wa, ba, out);
}

// round 7
// speedup vs baseline: 1.0894x; 1.0894x over previous
#include <cuda_runtime.h>
#include <cstdint>
#include <math.h>

#define B_   64
#define T_   512
#define D_   1024
#define H_   1024
#define NG   4096        // 4*H
#define CHUNK 64         // h k-slice per pipeline stage (per warpgroup)
#define HS_STRIDE 68     // padded floats per h row (64 + 4) -> bank-conflict-free
#define NCH  8           // chunks per warpgroup (512 / 64)
// smem: ws = 32*1024 floats (128KB, full w slice), hs = 2 wg * 2 buf * 64*68 floats
#define HS_FLOATS (2 * 2 * 64 * HS_STRIDE)
#define SMEM_LSTM ((32 * 1024 + HS_FLOATS) * 4)   // 205,056 bytes

// ---------------- static device scratch (no allocations allowed) ----------------
__device__ float g_xg[(size_t)T_ * B_ * NG];   // [t][b][4H] : x @ w_ih^T + b_ih + b_hh
__device__ float g_ht[2][B_ * H_];             // ping-pong h, [b][k] layout
__device__ float g_c[B_ * H_];                 // cell state,  [b][j] layout

// ---------------- f32x2 packed-math helpers (FFMA2 path, 2x fp32 rate) ----------
typedef unsigned long long ull;

__device__ __forceinline__ void fma2(ull& acc, ull a, ull b) {
    asm("fma.rn.f32x2 %0, %1, %2, %0;" : "+l"(acc) : "l"(a), "l"(b));
}
__device__ __forceinline__ void add2(ull& acc, ull b) {
    asm("add.rn.f32x2 %0, %0, %1;" : "+l"(acc) : "l"(b));
}
__device__ __forceinline__ ull dup2(float a) {
    ull r; asm("mov.b64 %0, {%1, %1};" : "=l"(r) : "f"(a)); return r;
}
__device__ __forceinline__ float2 unpk(ull v) {
    float2 r; asm("mov.b64 {%0, %1}, %2;" : "=f"(r.x), "=f"(r.y) : "l"(v)); return r;
}
__device__ __forceinline__ float redu2(ull v) { float2 p = unpk(v); return p.x + p.y; }

__device__ __forceinline__ void cp_async16(float* s, const float* g) {
    unsigned saddr = (unsigned)__cvta_generic_to_shared(s);
    asm volatile("cp.async.cg.shared.global [%0], [%1], 16;" :: "r"(saddr), "l"(g));
}
#define CP_COMMIT() asm volatile("cp.async.commit_group;" ::: "memory")

// =================================================================================
// Kernel 0: zero h0 and c
// =================================================================================
__global__ void zero_init() {
    int i = blockIdx.x * blockDim.x + threadIdx.x;
    if (i < B_ * H_) { g_ht[0][i] = 0.f; g_c[i] = 0.f; }
}

// =================================================================================
// Kernel A: xg[t][b][n] = sum_d x[b,t,d] * w_ih[n,d] + b_ih[n] + b_hh[n]
// 128x128x8 fp32 SGEMM, 256 threads, 8x8 per thread via f32x2 (pack along N).
// (Measured near the FFMA2 roofline — unchanged.)
// =================================================================================
__global__ __launch_bounds__(256) void sgemm_ih(
    const float* __restrict__ X, const float* __restrict__ W,
    const float* __restrict__ bih, const float* __restrict__ bhh)
{
    __shared__ float As[8][128];
    __shared__ float Bs[8][128];
    const int tid = threadIdx.x;
    const int m0 = blockIdx.y * 128;
    const int n0 = blockIdx.x * 128;
    const int lr = tid >> 1;
    const int lk = (tid & 1) << 2;
    const float* Ag = X + (size_t)(m0 + lr) * D_ + lk;
    const float* Bg = W + (size_t)(n0 + lr) * D_ + lk;
    const int tx = tid & 15;
    const int ty = tid >> 4;
    const int rm = ty << 2;
    const int rn = tx << 2;

    ull acc2[8][4];
    #pragma unroll
    for (int i = 0; i < 8; i++)
        #pragma unroll
        for (int j = 0; j < 4; j++) acc2[i][j] = 0ull;

    float4 av = *(const float4*)Ag;
    float4 bv = *(const float4*)Bg;

    for (int k0 = 0; k0 < D_; k0 += 8) {
        As[lk+0][lr] = av.x; As[lk+1][lr] = av.y; As[lk+2][lr] = av.z; As[lk+3][lr] = av.w;
        Bs[lk+0][lr] = bv.x; Bs[lk+1][lr] = bv.y; Bs[lk+2][lr] = bv.z; Bs[lk+3][lr] = bv.w;
        __syncthreads();
        if (k0 + 8 < D_) {
            av = *(const float4*)(Ag + k0 + 8);
            bv = *(const float4*)(Bg + k0 + 8);
        }
        #pragma unroll
        for (int k = 0; k < 8; k++) {
            float a[8];
            *(float4*)&a[0] = *(const float4*)&As[k][rm];
            *(float4*)&a[4] = *(const float4*)&As[k][rm + 64];
            ulonglong2 bA = *(const ulonglong2*)&Bs[k][rn];
            ulonglong2 bB = *(const ulonglong2*)&Bs[k][rn + 64];
            #pragma unroll
            for (int i = 0; i < 8; i++) {
                ull ad = dup2(a[i]);
                fma2(acc2[i][0], ad, bA.x);
                fma2(acc2[i][1], ad, bA.y);
                fma2(acc2[i][2], ad, bB.x);
                fma2(acc2[i][3], ad, bB.y);
            }
        }
        __syncthreads();
    }

    float biasv[8];
    #pragma unroll
    for (int j = 0; j < 8; j++) {
        int n = n0 + ((j < 4) ? (rn + j) : (64 + rn + j - 4));
        biasv[j] = bih[n] + bhh[n];
    }
    #pragma unroll
    for (int i = 0; i < 8; i++) {
        int m = m0 + ((i < 4) ? (rm + i) : (64 + rm + i - 4));
        int bb = m >> 9;
        int tt = m & 511;
        float* dst = g_xg + (size_t)(tt * B_ + bb) * NG;
        float2 u0 = unpk(acc2[i][0]), u1 = unpk(acc2[i][1]);
        float2 u2 = unpk(acc2[i][2]), u3 = unpk(acc2[i][3]);
        float4 v0 = make_float4(u0.x + biasv[0], u0.y + biasv[1],
                                u1.x + biasv[2], u1.y + biasv[3]);
        float4 v1 = make_float4(u2.x + biasv[4], u2.y + biasv[5],
                                u3.x + biasv[6], u3.y + biasv[7]);
        *(float4*)(dst + n0 + rn)      = v0;
        *(float4*)(dst + n0 + 64 + rn) = v1;
    }
}

// =================================================================================
// Kernel B: ONE LSTM timestep. 128 blocks x 256 threads (2 warpgroups, K-split).
// Block bid owns h columns j0=bid*8 .. +8 (all 64 batches, 4 gates).
// Warpgroup wg handles k in [wg*512, wg*512+512); within a wg, thread (tb,tg):
// 4 batches x col (j0+tg) x 4 gates -> 16 f32x2 accumulators; per k-quad:
// 8 LDS.128 + 32 FFMA2 (fma-issue-bound). Each wg runs its OWN cp.async h
// pipeline (named barrier), so the two wgs never sync until the final reduce.
// w slice staged in 8 per-chunk commit groups -> compute starts after ~24KB.
// =================================================================================
__global__ __launch_bounds__(256, 1) void lstm_step(const float* __restrict__ whh, int t)
{
    extern __shared__ float smem[];
    float* ws = smem;                       // 32 x 1024 floats, XOR-swizzled by col q
    float* hs = smem + 32 * 1024;           // per-wg double-buffered h staging
    const int tid = threadIdx.x;
    const int wg  = tid >> 7;               // 0 or 1
    const int lt  = tid & 127;
    const int tb  = lt >> 3;                // 0..15  batch quad
    const int tg  = lt & 7;                 // 0..7   col within block
    const int j0  = blockIdx.x * 8;
    const int j   = j0 + tg;
    const int kw0 = wg << 9;                // k offset of this warpgroup

    float* hs_wg = hs + wg * (2 * 64 * HS_STRIDE);

    const float* ht_r = g_ht[t & 1];
    float*       ht_w = g_ht[(t + 1) & 1];

    // --- prologue: 8 groups = w chunk c (+ h chunk 0 inside group 0) ---
    #pragma unroll 1
    for (int c = 0; c < NCH; c++) {
        #pragma unroll
        for (int z = 0; z < 4; z++) {
            int idx = lt + (z << 7);        // 0..511
            int r   = idx >> 4;             // local row 0..31,  r = g*8 + q
            int g   = r >> 3, q = r & 7;
            int kf  = kw0 + (c << 6) + ((idx & 15) << 2);
            cp_async16(ws + r * 1024 + (kf ^ (q << 2)),
                       whh + (size_t)(g * H_ + j0 + q) * H_ + kf);
        }
        if (c == 0) {
            #pragma unroll
            for (int z = 0; z < 8; z++) {
                int idx = lt + (z << 7);    // 0..1023
                int b = idx >> 4, f4 = (idx & 15) << 2;
                cp_async16(hs_wg + b * HS_STRIDE + f4,
                           ht_r + (size_t)b * H_ + kw0 + f4);
            }
        }
        CP_COMMIT();
    }

    // --- prefetch xg gate contributions + cell state (wg0 only) ---
    float xv[4][4];
    float cst[4];
    if (wg == 0) {
        const float* xb = g_xg + (size_t)(t * B_) * NG + j;
        #pragma unroll
        for (int i = 0; i < 4; i++) {
            int b = (tb << 2) + i;
            const float* p = xb + (size_t)b * NG;
            xv[i][0] = p[0]; xv[i][1] = p[H_]; xv[i][2] = p[2 * H_]; xv[i][3] = p[3 * H_];
            cst[i] = g_c[b * H_ + j];
        }
    }

    ull acc[4][4];
    #pragma unroll
    for (int i = 0; i < 4; i++)
        #pragma unroll
        for (int g = 0; g < 4; g++) acc[i][g] = 0ull;

    // --- main loop: per-wg independent double-buffered pipeline ---
    #pragma unroll 1
    for (int c = 0; c < NCH; c++) {
        if (c == 0) asm volatile("cp.async.wait_group 7;" ::: "memory");
        else        asm volatile("cp.async.wait_group 0;" ::: "memory");
        asm volatile("bar.sync %0, 128;" :: "r"(wg + 1) : "memory");

        if (c + 1 < NCH) {                  // prefetch next h chunk
            float* dst = hs_wg + ((c + 1) & 1) * (64 * HS_STRIDE);
            const float* src = ht_r + kw0 + ((c + 1) << 6);
            #pragma unroll
            for (int z = 0; z < 8; z++) {
                int idx = lt + (z << 7);
                int b = idx >> 4, f4 = (idx & 15) << 2;
                cp_async16(dst + b * HS_STRIDE + f4, src + (size_t)b * H_ + f4);
            }
            CP_COMMIT();
        }

        const float* hb = hs_wg + (c & 1) * (64 * HS_STRIDE) + (tb << 2) * HS_STRIDE;
        const int kg = kw0 + (c << 6);
        #pragma unroll 4
        for (int kk = 0; kk < CHUNK; kk += 4) {
            ulonglong2 hv[4];
            #pragma unroll
            for (int i = 0; i < 4; i++)
                hv[i] = *(const ulonglong2*)(hb + i * HS_STRIDE + kk);
            ulonglong2 wv[4];
            const int kidx = (kg + kk) ^ (tg << 2);
            #pragma unroll
            for (int g = 0; g < 4; g++)
                wv[g] = *(const ulonglong2*)(ws + (g * 8 + tg) * 1024 + kidx);
            #pragma unroll
            for (int i = 0; i < 4; i++) {
                #pragma unroll
                for (int g = 0; g < 4; g++) {
                    fma2(acc[i][g], hv[i].x, wv[g].x);
                    fma2(acc[i][g], hv[i].y, wv[g].y);
                }
            }
        }
    }

    // --- cross-warpgroup reduction (wg1 partials -> wg0) ---
    __syncthreads();
    ull* red = (ull*)hs;                    // 16KB scratch (h staging is dead now)
    if (wg == 1) {
        #pragma unroll
        for (int a = 0; a < 16; a++)
            red[lt * 16 + a] = ((ull*)acc)[a];
    }
    __syncthreads();

    if (wg == 0) {
        #pragma unroll
        for (int a = 0; a < 16; a++)
            add2(((ull*)acc)[a], red[lt * 16 + a]);

        // gates + pointwise cell update
        #pragma unroll
        for (int i = 0; i < 4; i++) {
            int b = (tb << 2) + i;
            float gi = redu2(acc[i][0]) + xv[i][0];
            float gf = redu2(acc[i][1]) + xv[i][1];
            float gg = redu2(acc[i][2]) + xv[i][2];
            float go = redu2(acc[i][3]) + xv[i][3];
            float s_i = 1.f / (1.f + expf(-gi));
            float s_f = 1.f / (1.f + expf(-gf));
            float t_g = tanhf(gg);
            float s_o = 1.f / (1.f + expf(-go));
            float cn  = s_f * cst[i] + s_i * t_g;
            g_c[b * H_ + j]  = cn;
            ht_w[b * H_ + j] = s_o * tanhf(cn);
        }
    }
}

// =================================================================================
// Kernel C: heads. h_final in g_ht[0], [b][k]. Output: gender[64,2] ++ age[64,7].
// =================================================================================
__global__ void heads_kernel(const float* __restrict__ wg, const float* __restrict__ bg,
                             const float* __restrict__ wa, const float* __restrict__ ba,
                             float* __restrict__ out)
{
    int o = blockIdx.x;        // 0..8  (0,1 -> gender; 2..8 -> age)
    int b = threadIdx.x;       // 0..63
    const float* w = (o < 2) ? (wg + o * H_) : (wa + (o - 2) * H_);
    float bias = (o < 2) ? bg[o] : ba[o - 2];
    const float* h = g_ht[0] + (size_t)b * H_;
    float s0 = 0.f, s1 = 0.f, s2 = 0.f, s3 = 0.f;
    for (int k = 0; k < H_; k += 4) {
        s0 += h[k + 0] * w[k + 0];
        s1 += h[k + 1] * w[k + 1];
        s2 += h[k + 2] * w[k + 2];
        s3 += h[k + 3] * w[k + 3];
    }
    float s = bias + ((s0 + s1) + (s2 + s3));
    if (o < 2) out[b * 2 + o] = s;
    else       out[B_ * 2 + b * 7 + (o - 2)] = s;
}

// =================================================================================
extern "C" void kernel_launch(void* const* d_in, const int* in_sizes, int n_in,
                              void* d_out, int out_size)
{
    const float* x   = (const float*)d_in[0];
    const float* wih = (const float*)d_in[1];
    const float* whh = (const float*)d_in[2];
    const float* bih = (const float*)d_in[3];
    const float* bhh = (const float*)d_in[4];
    const float* wg  = (const float*)d_in[5];
    const float* bg  = (const float*)d_in[6];
    const float* wa  = (const float*)d_in[7];
    const float* ba  = (const float*)d_in[8];
    float* out = (float*)d_out;

    static int smem_set = 0;
    if (!smem_set) {
        cudaFuncSetAttribute(lstm_step, cudaFuncAttributeMaxDynamicSharedMemorySize, SMEM_LSTM);
        smem_set = 1;
    }

    zero_init<<<(B_ * H_ + 255) / 256, 256>>>();

    dim3 gA(NG / 128, (B_ * T_) / 128);          // 32 x 256 blocks
    sgemm_ih<<<gA, 256>>>(x, wih, bih, bhh);

    for (int t = 0; t < T_; t++)
        lstm_step<<<128, 256, SMEM_LSTM>>>(whh, t);

    heads_kernel<<<9, 64>>>(wg, bg, wa, ba, out);
}